// round 2
// baseline (speedup 1.0000x reference)
#include <cuda_runtime.h>

// YoloV3Decoder: predictions (1, 145152, 85) fp32 -> tuple flattened as fp32:
//   [0 .. 4N)          bboxes  (x,y,w,h per anchor)
//   [4N .. 5N)         scores  (objectness * class_conf)
//   [5N .. 6N)         class_pred (argmax index as float)
//   [6N .. 12N)        detections (x,y,w,h,class_conf,class_pred per anchor)
// score_threshold input is unused by the reference outputs.

#define NUM_ANCHORS 145152
#define NUM_CH 85
#define NUM_CLASSES 80
#define ROWS_PER_BLOCK 128
#define THREADS 128

static __device__ __forceinline__ float inv_img() { return 1.0f / 1536.0f; }

__global__ __launch_bounds__(THREADS) void yolo_decode_kernel(
    const float* __restrict__ pred, float* __restrict__ out)
{
    __shared__ float tile[ROWS_PER_BLOCK * NUM_CH];  // 43520 bytes

    const int base_row = blockIdx.x * ROWS_PER_BLOCK;

    // Coalesced staging: 128 rows * 85 floats = 10880 floats = 2720 float4.
    // Tile base offset = base_row*85 floats = blockIdx*43520 bytes (16B aligned).
    {
        const float4* __restrict__ src =
            reinterpret_cast<const float4*>(pred + (size_t)base_row * NUM_CH);
        float4* __restrict__ dst = reinterpret_cast<float4*>(tile);
        const int n4 = ROWS_PER_BLOCK * NUM_CH / 4;  // 2720
        #pragma unroll 4
        for (int i = threadIdx.x; i < n4; i += THREADS) {
            dst[i] = src[i];
        }
    }
    __syncthreads();

    const int a = base_row + threadIdx.x;          // global anchor id
    const float* __restrict__ row = tile + threadIdx.x * NUM_CH;  // stride 85 words: conflict-free

    const float bx = row[0] * inv_img();
    const float by = row[1] * inv_img();
    const float bw = row[2] * inv_img();
    const float bh = row[3] * inv_img();
    const float obj = row[4];

    // argmax over classes [5, 85): first-occurrence on ties (strict >)
    float cmax = row[5];
    int cidx = 0;
    #pragma unroll
    for (int c = 1; c < NUM_CLASSES; ++c) {
        const float v = row[5 + c];
        if (v > cmax) { cmax = v; cidx = c; }
    }

    const float x = bx - bw * 0.5f;
    const float y = by - bh * 0.5f;
    const float w = bx + bw * 0.5f;
    const float h = by + bh * 0.5f;
    const float score = obj * cmax;
    const float cls_f = (float)cidx;

    // bboxes: one float4 per anchor, coalesced
    reinterpret_cast<float4*>(out)[a] = make_float4(x, y, w, h);
    // scores
    out[(size_t)NUM_ANCHORS * 4 + a] = score;
    // class_pred
    out[(size_t)NUM_ANCHORS * 5 + a] = cls_f;
    // detections: 6 floats per anchor
    float* __restrict__ det = out + (size_t)NUM_ANCHORS * 6 + (size_t)a * 6;
    det[0] = x; det[1] = y; det[2] = w; det[3] = h;
    det[4] = cmax; det[5] = cls_f;
}

extern "C" void kernel_launch(void* const* d_in, const int* in_sizes, int n_in,
                              void* d_out, int out_size)
{
    const float* pred = (const float*)d_in[0];
    // d_in[1] = score_threshold: unused by the reference outputs.
    float* out = (float*)d_out;

    const int blocks = NUM_ANCHORS / ROWS_PER_BLOCK;  // 1134
    yolo_decode_kernel<<<blocks, THREADS>>>(pred, out);
}